// round 8
// baseline (speedup 1.0000x reference)
#include <cuda_runtime.h>
#include <math.h>

#define LDIM 96           // L
#define FDIM 192          // 2L
#define TILE_R 64         // rows per tile
#define NTHREADS 512
#define PAD 65            // odd pad -> conflict-free strided smem access

// Folded DCT * W1 matrix (96 x 192), recomputed every launch (deterministic).
__device__ float g_M1[LDIM * FDIM];

// M1[n][j] = sum_f 2*cos(pi*(2n+1)*f/(2*96)) * W1[f][j], fp64 accumulation.
__global__ void precompute_m1_kernel(const float* __restrict__ W1) {
    int n = blockIdx.x;    // 0..95
    int j = threadIdx.x;   // 0..191
    double base = 3.14159265358979323846 * (2.0 * (double)n + 1.0) / (2.0 * (double)LDIM);
    double acc = 0.0;
    for (int f = 0; f < LDIM; ++f) {
        acc += 2.0 * cos(base * (double)f) * (double)W1[f * FDIM + j];
    }
    g_M1[n * FDIM + j] = (float)acc;
}

__global__ void __launch_bounds__(NTHREADS, 1)
fused_dct_mlp_ln_kernel(const float* __restrict__ x,
                        const float* __restrict__ W2,
                        const float* __restrict__ gamma,
                        const float* __restrict__ beta,
                        float* __restrict__ out,
                        int ntiles)
{
    extern __shared__ float smv[];
    float* M1s = smv;                          // [96][192]   73,728 B
    float* W2s = M1s + LDIM * FDIM;            // [192][96]   73,728 B
    float* Xs  = W2s + FDIM * LDIM;            // [96][PAD]   24,960 B  (k-major, transposed)
    float* Hs  = Xs + LDIM * PAD;              // [192][PAD]  49,920 B  (k-major, transposed)

    const int tid  = threadIdx.x;
    const int lane = tid & 31;
    const int wid  = tid >> 5;        // 0..15; each warp owns 4 rows
    const int r0   = wid * 4;

    // Load weights into smem ONCE per block (persistent blocks).
    for (int i = tid; i < LDIM * FDIM; i += NTHREADS) M1s[i] = g_M1[i];
    for (int i = tid; i < FDIM * LDIM; i += NTHREADS) W2s[i] = W2[i];
    float gm[3], bt[3];
    #pragma unroll
    for (int i = 0; i < 3; ++i) {
        gm[i] = gamma[lane + 32 * i];
        bt[i] = beta[lane + 32 * i];
    }
    __syncthreads();

    for (int tile = blockIdx.x; tile < ntiles; tile += gridDim.x) {
        // ---- Load X tile (64 x 96) transposed into Xs[k][r], float4 from gmem ----
        {
            const float4* xg4 = (const float4*)(x + (size_t)tile * (TILE_R * LDIM));
            #pragma unroll
            for (int j = 0; j < (TILE_R * LDIM / 4) / NTHREADS; ++j) {  // 3 iters
                int i4 = tid + j * NTHREADS;
                float4 v = xg4[i4];
                int e = i4 * 4;
                int r = e / LDIM;
                int c = e - r * LDIM;    // 96 % 4 == 0 -> never crosses row
                Xs[(c + 0) * PAD + r] = v.x;
                Xs[(c + 1) * PAD + r] = v.y;
                Xs[(c + 2) * PAD + r] = v.z;
                Xs[(c + 3) * PAD + r] = v.w;
            }
        }
        __syncthreads();

        // ---- GEMM1: H(64x192) = relu( X(64x96) @ M1(96x192) ) ----
        {
            float acc[4][6];
            #pragma unroll
            for (int ii = 0; ii < 4; ++ii)
                #pragma unroll
                for (int i = 0; i < 6; ++i) acc[ii][i] = 0.f;

            #pragma unroll 4
            for (int k = 0; k < LDIM; ++k) {
                float a0 = Xs[k * PAD + r0 + 0];   // warp-broadcast loads
                float a1 = Xs[k * PAD + r0 + 1];
                float a2 = Xs[k * PAD + r0 + 2];
                float a3 = Xs[k * PAD + r0 + 3];
                const float* mrow = &M1s[k * FDIM + lane];
                #pragma unroll
                for (int i = 0; i < 6; ++i) {
                    float b = mrow[32 * i];        // lane-stride 1: conflict-free
                    acc[0][i] += a0 * b;
                    acc[1][i] += a1 * b;
                    acc[2][i] += a2 * b;
                    acc[3][i] += a3 * b;
                }
            }
            #pragma unroll
            for (int ii = 0; ii < 4; ++ii)
                #pragma unroll
                for (int i = 0; i < 6; ++i)
                    Hs[(lane + 32 * i) * PAD + (r0 + ii)] = fmaxf(acc[ii][i], 0.f);
        }
        __syncthreads();

        // ---- GEMM2 + sigmoid + LayerNorm + x*lr ----
        {
            float acc[4][3];
            #pragma unroll
            for (int ii = 0; ii < 4; ++ii)
                #pragma unroll
                for (int i = 0; i < 3; ++i) acc[ii][i] = 0.f;

            #pragma unroll 4
            for (int k = 0; k < FDIM; ++k) {
                float a0 = Hs[k * PAD + r0 + 0];
                float a1 = Hs[k * PAD + r0 + 1];
                float a2 = Hs[k * PAD + r0 + 2];
                float a3 = Hs[k * PAD + r0 + 3];
                const float* wrow = &W2s[k * LDIM + lane];
                #pragma unroll
                for (int i = 0; i < 3; ++i) {
                    float b = wrow[32 * i];
                    acc[0][i] += a0 * b;
                    acc[1][i] += a1 * b;
                    acc[2][i] += a2 * b;
                    acc[3][i] += a3 * b;
                }
            }

            #pragma unroll
            for (int ii = 0; ii < 4; ++ii) {
                // sigmoid
                float v0 = 1.f / (1.f + expf(-acc[ii][0]));
                float v1 = 1.f / (1.f + expf(-acc[ii][1]));
                float v2 = 1.f / (1.f + expf(-acc[ii][2]));

                // LayerNorm over 96 (this warp holds the whole row: 32 lanes x 3)
                float s = v0 + v1 + v2;
                #pragma unroll
                for (int o = 16; o > 0; o >>= 1)
                    s += __shfl_xor_sync(0xffffffffu, s, o);
                float mu = s * (1.f / 96.f);

                float d0 = v0 - mu, d1 = v1 - mu, d2 = v2 - mu;
                float q = d0 * d0 + d1 * d1 + d2 * d2;
                #pragma unroll
                for (int o = 16; o > 0; o >>= 1)
                    q += __shfl_xor_sync(0xffffffffu, q, o);
                float inv = rsqrtf(q * (1.f / 96.f) + 1e-6f);

                size_t obase = ((size_t)tile * TILE_R + (size_t)(r0 + ii)) * LDIM;
                int r = r0 + ii;
                // out = x * ((lr - mu)*inv*gamma + beta); coalesced 128B stores
                out[obase + lane]      = Xs[(lane)      * PAD + r] * (d0 * inv * gm[0] + bt[0]);
                out[obase + lane + 32] = Xs[(lane + 32) * PAD + r] * (d1 * inv * gm[1] + bt[1]);
                out[obase + lane + 64] = Xs[(lane + 64) * PAD + r] * (d2 * inv * gm[2] + bt[2]);
            }
        }
        __syncthreads();   // protect Xs/Hs before next tile overwrites
    }
}

extern "C" void kernel_launch(void* const* d_in, const int* in_sizes, int n_in,
                              void* d_out, int out_size) {
    const float* x     = (const float*)d_in[0];
    const float* W1    = (const float*)d_in[1];
    const float* W2    = (const float*)d_in[2];
    const float* gamma = (const float*)d_in[3];
    const float* beta  = (const float*)d_in[4];
    float* out = (float*)d_out;

    int rows   = in_sizes[0] / LDIM;     // B*C = 786432
    int ntiles = rows / TILE_R;          // 12288

    // Fold DCT into W1 (tiny kernel, runs every launch -> deterministic)
    precompute_m1_kernel<<<LDIM, FDIM>>>(W1);

    const size_t smem_bytes =
        (size_t)(LDIM * FDIM + FDIM * LDIM + LDIM * PAD + FDIM * PAD) * sizeof(float); // 222,336 B
    cudaFuncSetAttribute(fused_dct_mlp_ln_kernel,
                         cudaFuncAttributeMaxDynamicSharedMemorySize,
                         (int)smem_bytes);

    int nsm = 148;
    cudaDeviceGetAttribute(&nsm, cudaDevAttrMultiProcessorCount, 0);
    int grid = nsm;
    if (grid > ntiles) grid = ntiles;

    fused_dct_mlp_ln_kernel<<<grid, NTHREADS, smem_bytes>>>(x, W2, gamma, beta, out, ntiles);
}

// round 9
// speedup vs baseline: 1.1530x; 1.1530x over previous
#include <cuda_runtime.h>
#include <math.h>

#define LDIM 96           // L
#define FDIM 192          // 2L
#define TILE_R 64         // rows per tile
#define NTHREADS 512
#define KP1 48            // k-pairs for GEMM1 (96/2)
#define KP2 96            // k-pairs for GEMM2 (192/2)
#define ROWPAD 66         // float2 row pitch for Xs2/Hs2 (even -> 16B-aligned LDS.128)

typedef unsigned long long ull;

// Folded DCT * W1 matrix (96 x 192), recomputed every launch (deterministic).
__device__ float g_M1[LDIM * FDIM];

// M1[n][j] = sum_f 2*cos(pi*(2n+1)*f/(2*96)) * W1[f][j], fp64 accumulation.
__global__ void precompute_m1_kernel(const float* __restrict__ W1) {
    int n = blockIdx.x;    // 0..95
    int j = threadIdx.x;   // 0..191
    double base = 3.14159265358979323846 * (2.0 * (double)n + 1.0) / (2.0 * (double)LDIM);
    double acc = 0.0;
    for (int f = 0; f < LDIM; ++f) {
        acc += 2.0 * cos(base * (double)f) * (double)W1[f * FDIM + j];
    }
    g_M1[n * FDIM + j] = (float)acc;
}

// packed fp32x2 FMA: d = a*b + d (componentwise), 2 FMAs / instruction
__device__ __forceinline__ void ffma2(ull& d, ull a, ull b) {
    asm volatile("fma.rn.f32x2 %0, %1, %2, %0;" : "+l"(d) : "l"(a), "l"(b));
}
__device__ __forceinline__ float f32x2_sum(ull v) {
    float lo, hi;
    asm("mov.b64 {%0, %1}, %2;" : "=f"(lo), "=f"(hi) : "l"(v));
    return lo + hi;
}

__global__ void __launch_bounds__(NTHREADS, 1)
fused_dct_mlp_ln_kernel(const float* __restrict__ x,
                        const float* __restrict__ W2,
                        const float* __restrict__ gamma,
                        const float* __restrict__ beta,
                        float* __restrict__ out,
                        int ntiles)
{
    // all staging in k-pair-packed float2 layout
    extern __shared__ float2 smv2[];
    float2* M1p = smv2;                          // [48][192] f2   73,728 B
    float2* W2p = M1p + KP1 * FDIM;              // [96][96]  f2   73,728 B
    float2* Xs2 = W2p + KP2 * LDIM;              // [48][66]  f2   25,344 B
    float2* Hs2 = Xs2 + KP1 * ROWPAD;            // [96][66]  f2   50,688 B
    const ull* M1u = (const ull*)M1p;
    const ull* W2u = (const ull*)W2p;
    const ull* Xsu = (const ull*)Xs2;
    const ull* Hsu = (const ull*)Hs2;
    float* Xsf = (float*)Xs2;                    // scalar view for output stage
    float* Hsf = (float*)Hs2;                    // scalar view for GEMM1 epilogue

    const int tid  = threadIdx.x;
    const int lane = tid & 31;
    const int wid  = tid >> 5;        // 0..15; each warp owns 4 rows
    const int r0   = wid * 4;

    // ---- One-time weight load, repacked into k-pair float2 layout ----
    {
        float* M1f = (float*)M1p;
        float* W2f = (float*)W2p;
        for (int i = tid; i < LDIM * FDIM; i += NTHREADS) {
            int k = i / FDIM, j = i - k * FDIM;
            M1f[(k >> 1) * (2 * FDIM) + 2 * j + (k & 1)] = g_M1[i];
        }
        for (int i = tid; i < FDIM * LDIM; i += NTHREADS) {
            int k = i / LDIM, n = i - k * LDIM;
            W2f[(k >> 1) * (2 * LDIM) + 2 * n + (k & 1)] = W2[i];
        }
    }
    float gm[3], bt[3];
    #pragma unroll
    for (int i = 0; i < 3; ++i) {
        gm[i] = gamma[lane + 32 * i];
        bt[i] = beta[lane + 32 * i];
    }
    __syncthreads();

    for (int tile = blockIdx.x; tile < ntiles; tile += gridDim.x) {
        // ---- Load X tile (64 x 96), k-pair pack + transpose into Xs2[kp][row] ----
        {
            const float4* xg4 = (const float4*)(x + (size_t)tile * (TILE_R * LDIM));
            #pragma unroll
            for (int j = 0; j < (TILE_R * LDIM / 4) / NTHREADS; ++j) {  // 3 iters
                int i4 = tid + j * NTHREADS;
                float4 v = xg4[i4];
                int e = i4 * 4;
                int r = e / LDIM;
                int c = e - r * LDIM;       // multiple of 4, never crosses row
                int q = c >> 1;             // even k-pair index
                Xs2[(q + 0) * ROWPAD + r] = make_float2(v.x, v.y);
                Xs2[(q + 1) * ROWPAD + r] = make_float2(v.z, v.w);
            }
        }
        __syncthreads();

        // ---- GEMM1: H(64x192) = relu( X @ M1 ), packed along k-pairs ----
        {
            ull acc[4][6];
            #pragma unroll
            for (int ii = 0; ii < 4; ++ii)
                #pragma unroll
                for (int i = 0; i < 6; ++i) acc[ii][i] = 0ull;

            #pragma unroll 4
            for (int c = 0; c < KP1; ++c) {
                // two broadcast LDS.128: rows r0..r0+3, packed (k_even,k_odd)
                ulonglong2 A01 = *(const ulonglong2*)&Xsu[c * ROWPAD + r0];
                ulonglong2 A23 = *(const ulonglong2*)&Xsu[c * ROWPAD + r0 + 2];
                const ull* brow = &M1u[c * FDIM + lane];
                #pragma unroll
                for (int i = 0; i < 6; ++i) {
                    ull b = brow[32 * i];          // LDS.64, lane-contiguous
                    ffma2(acc[0][i], A01.x, b);
                    ffma2(acc[1][i], A01.y, b);
                    ffma2(acc[2][i], A23.x, b);
                    ffma2(acc[3][i], A23.y, b);
                }
            }
            // epilogue: reduce pair, relu, store into k-pair-packed Hs2
            #pragma unroll
            for (int ii = 0; ii < 4; ++ii) {
                int rr = (r0 + ii) << 1;
                #pragma unroll
                for (int i = 0; i < 6; ++i) {
                    float h = fmaxf(f32x2_sum(acc[ii][i]), 0.f);
                    int col = lane + 32 * i;
                    Hsf[(col >> 1) * (2 * ROWPAD) + rr + (col & 1)] = h;
                }
            }
        }
        __syncthreads();

        // ---- GEMM2 + sigmoid + LayerNorm + x*lr ----
        {
            ull acc[4][3];
            #pragma unroll
            for (int ii = 0; ii < 4; ++ii)
                #pragma unroll
                for (int i = 0; i < 3; ++i) acc[ii][i] = 0ull;

            #pragma unroll 4
            for (int c = 0; c < KP2; ++c) {
                ulonglong2 A01 = *(const ulonglong2*)&Hsu[c * ROWPAD + r0];
                ulonglong2 A23 = *(const ulonglong2*)&Hsu[c * ROWPAD + r0 + 2];
                const ull* wrow = &W2u[c * LDIM + lane];
                #pragma unroll
                for (int i = 0; i < 3; ++i) {
                    ull b = wrow[32 * i];
                    ffma2(acc[0][i], A01.x, b);
                    ffma2(acc[1][i], A01.y, b);
                    ffma2(acc[2][i], A23.x, b);
                    ffma2(acc[3][i], A23.y, b);
                }
            }

            #pragma unroll
            for (int ii = 0; ii < 4; ++ii) {
                // sigmoid (fast exp: MUFU-based, ~1e-6 rel err, tolerance 1e-3)
                float v0 = __fdividef(1.f, 1.f + __expf(-f32x2_sum(acc[ii][0])));
                float v1 = __fdividef(1.f, 1.f + __expf(-f32x2_sum(acc[ii][1])));
                float v2 = __fdividef(1.f, 1.f + __expf(-f32x2_sum(acc[ii][2])));

                // LayerNorm over 96 (warp holds whole row: 32 lanes x 3)
                float s = v0 + v1 + v2;
                #pragma unroll
                for (int o = 16; o > 0; o >>= 1)
                    s += __shfl_xor_sync(0xffffffffu, s, o);
                float mu = s * (1.f / 96.f);

                float d0 = v0 - mu, d1 = v1 - mu, d2 = v2 - mu;
                float q = d0 * d0 + d1 * d1 + d2 * d2;
                #pragma unroll
                for (int o = 16; o > 0; o >>= 1)
                    q += __shfl_xor_sync(0xffffffffu, q, o);
                float inv = rsqrtf(q * (1.f / 96.f) + 1e-6f);

                int r = r0 + ii;
                int rr = r << 1;
                size_t obase = ((size_t)tile * TILE_R + (size_t)r) * LDIM;
                // re-read x from packed Xs2 (scalar view), coalesced 128B stores
                #pragma unroll
                for (int j = 0; j < 3; ++j) {
                    float d = (j == 0) ? d0 : (j == 1) ? d1 : d2;
                    int col = lane + 32 * j;
                    float xv = Xsf[(col >> 1) * (2 * ROWPAD) + rr + (col & 1)];
                    out[obase + col] = xv * (d * inv * gm[j] + bt[j]);
                }
            }
        }
        __syncthreads();   // protect Xs2/Hs2 before next tile overwrites
    }
}

extern "C" void kernel_launch(void* const* d_in, const int* in_sizes, int n_in,
                              void* d_out, int out_size) {
    const float* x     = (const float*)d_in[0];
    const float* W1    = (const float*)d_in[1];
    const float* W2    = (const float*)d_in[2];
    const float* gamma = (const float*)d_in[3];
    const float* beta  = (const float*)d_in[4];
    float* out = (float*)d_out;

    int rows   = in_sizes[0] / LDIM;     // B*C = 786432
    int ntiles = rows / TILE_R;          // 12288

    precompute_m1_kernel<<<LDIM, FDIM>>>(W1);

    const size_t smem_bytes =
        (size_t)(KP1 * FDIM + KP2 * LDIM + KP1 * ROWPAD + KP2 * ROWPAD) * sizeof(float2); // 223,488 B
    cudaFuncSetAttribute(fused_dct_mlp_ln_kernel,
                         cudaFuncAttributeMaxDynamicSharedMemorySize,
                         (int)smem_bytes);

    int nsm = 148;
    cudaDeviceGetAttribute(&nsm, cudaDevAttrMultiProcessorCount, 0);
    int grid = nsm;
    if (grid > ntiles) grid = ntiles;

    fused_dct_mlp_ln_kernel<<<grid, NTHREADS, smem_bytes>>>(x, W2, gamma, beta, out, ntiles);
}

// round 10
// speedup vs baseline: 1.2480x; 1.0824x over previous
#include <cuda_runtime.h>
#include <math.h>

#define LDIM 96           // L
#define FDIM 192          // 2L
#define TILE_R 64         // rows per tile
#define NTHREADS 256      // 8 warps, TM=8 rows/warp -> 256-reg/thread ceiling
#define TM 8
#define KP1 48            // k-pairs for GEMM1 (96/2)
#define KP2 96            // k-pairs for GEMM2 (192/2)
#define ROWPAD 66         // float2 row pitch (even -> 16B-aligned LDS.128)

typedef unsigned long long ull;

// Folded DCT * W1 matrix (96 x 192), recomputed every launch (deterministic).
__device__ float g_M1[LDIM * FDIM];

__global__ void precompute_m1_kernel(const float* __restrict__ W1) {
    int n = blockIdx.x;    // 0..95
    int j = threadIdx.x;   // 0..191
    double base = 3.14159265358979323846 * (2.0 * (double)n + 1.0) / (2.0 * (double)LDIM);
    double acc = 0.0;
    for (int f = 0; f < LDIM; ++f)
        acc += 2.0 * cos(base * (double)f) * (double)W1[f * FDIM + j];
    g_M1[n * FDIM + j] = (float)acc;
}

// packed fp32x2 FMA: d = a*b + d (componentwise)
__device__ __forceinline__ void ffma2(ull& d, ull a, ull b) {
    asm volatile("fma.rn.f32x2 %0, %1, %2, %0;" : "+l"(d) : "l"(a), "l"(b));
}
__device__ __forceinline__ float f32x2_sum(ull v) {
    float lo, hi;
    asm("mov.b64 {%0, %1}, %2;" : "=f"(lo), "=f"(hi) : "l"(v));
    return lo + hi;
}

__global__ void __launch_bounds__(NTHREADS, 1)
fused_dct_mlp_ln_kernel(const float* __restrict__ x,
                        const float* __restrict__ W2,
                        const float* __restrict__ gamma,
                        const float* __restrict__ beta,
                        float* __restrict__ out,
                        int ntiles)
{
    extern __shared__ float2 smv2[];
    float2* M1p = smv2;                          // [48][192] f2   73,728 B
    float2* W2p = M1p + KP1 * FDIM;              // [96][96]  f2   73,728 B
    float2* Xs2 = W2p + KP2 * LDIM;              // [48][66]  f2   25,344 B
    float2* Hs2 = Xs2 + KP1 * ROWPAD;            // [96][66]  f2   50,688 B
    const ull* M1u = (const ull*)M1p;
    const ull* W2u = (const ull*)W2p;
    const ull* Xsu = (const ull*)Xs2;
    const ull* Hsu = (const ull*)Hs2;
    float* Xsf = (float*)Xs2;
    float* Hsf = (float*)Hs2;

    const int tid  = threadIdx.x;
    const int lane = tid & 31;
    const int wid  = tid >> 5;        // 0..7; each warp owns TM=8 rows
    const int r0   = wid * TM;

    // ---- One-time weight load, k-pair float2 repack ----
    {
        float* M1f = (float*)M1p;
        float* W2f = (float*)W2p;
        for (int i = tid; i < LDIM * FDIM; i += NTHREADS) {
            int k = i / FDIM, j = i - k * FDIM;
            M1f[(k >> 1) * (2 * FDIM) + 2 * j + (k & 1)] = g_M1[i];
        }
        for (int i = tid; i < FDIM * LDIM; i += NTHREADS) {
            int k = i / LDIM, n = i - k * LDIM;
            W2f[(k >> 1) * (2 * LDIM) + 2 * n + (k & 1)] = W2[i];
        }
    }
    float gm[3], bt[3];
    #pragma unroll
    for (int i = 0; i < 3; ++i) {
        gm[i] = gamma[lane + 32 * i];
        bt[i] = beta[lane + 32 * i];
    }
    __syncthreads();

    for (int tile = blockIdx.x; tile < ntiles; tile += gridDim.x) {
        // ---- Load X tile (64 x 96), k-pair pack + transpose into Xs2[kp][row] ----
        {
            const float4* xg4 = (const float4*)(x + (size_t)tile * (TILE_R * LDIM));
            #pragma unroll
            for (int j = 0; j < (TILE_R * LDIM / 4) / NTHREADS; ++j) {  // 6 iters
                int i4 = tid + j * NTHREADS;
                float4 v = xg4[i4];
                int e = i4 * 4;
                int r = e / LDIM;
                int c = e - r * LDIM;       // multiple of 4, never crosses row
                int q = c >> 1;
                Xs2[(q + 0) * ROWPAD + r] = make_float2(v.x, v.y);
                Xs2[(q + 1) * ROWPAD + r] = make_float2(v.z, v.w);
            }
        }
        __syncthreads();

        // ---- GEMM1: H(64x192) = relu( X @ M1 ), TM=8 x TN=6 ----
        {
            ull acc[TM][6];
            #pragma unroll
            for (int ii = 0; ii < TM; ++ii)
                #pragma unroll
                for (int i = 0; i < 6; ++i) acc[ii][i] = 0ull;

            #pragma unroll 2
            for (int c = 0; c < KP1; ++c) {
                // 4 broadcast LDS.128: rows r0..r0+7, packed (k_even,k_odd)
                ulonglong2 A01 = *(const ulonglong2*)&Xsu[c * ROWPAD + r0];
                ulonglong2 A23 = *(const ulonglong2*)&Xsu[c * ROWPAD + r0 + 2];
                ulonglong2 A45 = *(const ulonglong2*)&Xsu[c * ROWPAD + r0 + 4];
                ulonglong2 A67 = *(const ulonglong2*)&Xsu[c * ROWPAD + r0 + 6];
                const ull* brow = &M1u[c * FDIM + lane];
                #pragma unroll
                for (int i = 0; i < 6; ++i) {
                    ull b = brow[32 * i];          // LDS.64, lane-contiguous
                    ffma2(acc[0][i], A01.x, b);
                    ffma2(acc[1][i], A01.y, b);
                    ffma2(acc[2][i], A23.x, b);
                    ffma2(acc[3][i], A23.y, b);
                    ffma2(acc[4][i], A45.x, b);
                    ffma2(acc[5][i], A45.y, b);
                    ffma2(acc[6][i], A67.x, b);
                    ffma2(acc[7][i], A67.y, b);
                }
            }
            #pragma unroll
            for (int ii = 0; ii < TM; ++ii) {
                int rr = (r0 + ii) << 1;
                #pragma unroll
                for (int i = 0; i < 6; ++i) {
                    float h = fmaxf(f32x2_sum(acc[ii][i]), 0.f);
                    int col = lane + 32 * i;
                    Hsf[(col >> 1) * (2 * ROWPAD) + rr + (col & 1)] = h;
                }
            }
        }
        __syncthreads();

        // ---- GEMM2 + sigmoid + LayerNorm + x*lr, TM=8 x TN=3 ----
        {
            ull acc[TM][3];
            #pragma unroll
            for (int ii = 0; ii < TM; ++ii)
                #pragma unroll
                for (int i = 0; i < 3; ++i) acc[ii][i] = 0ull;

            #pragma unroll 2
            for (int c = 0; c < KP2; ++c) {
                ulonglong2 A01 = *(const ulonglong2*)&Hsu[c * ROWPAD + r0];
                ulonglong2 A23 = *(const ulonglong2*)&Hsu[c * ROWPAD + r0 + 2];
                ulonglong2 A45 = *(const ulonglong2*)&Hsu[c * ROWPAD + r0 + 4];
                ulonglong2 A67 = *(const ulonglong2*)&Hsu[c * ROWPAD + r0 + 6];
                const ull* wrow = &W2u[c * LDIM + lane];
                #pragma unroll
                for (int i = 0; i < 3; ++i) {
                    ull b = wrow[32 * i];
                    ffma2(acc[0][i], A01.x, b);
                    ffma2(acc[1][i], A01.y, b);
                    ffma2(acc[2][i], A23.x, b);
                    ffma2(acc[3][i], A23.y, b);
                    ffma2(acc[4][i], A45.x, b);
                    ffma2(acc[5][i], A45.y, b);
                    ffma2(acc[6][i], A67.x, b);
                    ffma2(acc[7][i], A67.y, b);
                }
            }

            #pragma unroll
            for (int ii = 0; ii < TM; ++ii) {
                float v0 = __fdividef(1.f, 1.f + __expf(-f32x2_sum(acc[ii][0])));
                float v1 = __fdividef(1.f, 1.f + __expf(-f32x2_sum(acc[ii][1])));
                float v2 = __fdividef(1.f, 1.f + __expf(-f32x2_sum(acc[ii][2])));

                float s = v0 + v1 + v2;
                #pragma unroll
                for (int o = 16; o > 0; o >>= 1)
                    s += __shfl_xor_sync(0xffffffffu, s, o);
                float mu = s * (1.f / 96.f);

                float d0 = v0 - mu, d1 = v1 - mu, d2 = v2 - mu;
                float q = d0 * d0 + d1 * d1 + d2 * d2;
                #pragma unroll
                for (int o = 16; o > 0; o >>= 1)
                    q += __shfl_xor_sync(0xffffffffu, q, o);
                float inv = rsqrtf(q * (1.f / 96.f) + 1e-6f);

                int r = r0 + ii;
                int rr = r << 1;
                size_t obase = ((size_t)tile * TILE_R + (size_t)r) * LDIM;
                #pragma unroll
                for (int j = 0; j < 3; ++j) {
                    float d = (j == 0) ? d0 : (j == 1) ? d1 : d2;
                    int col = lane + 32 * j;
                    float xv = Xsf[(col >> 1) * (2 * ROWPAD) + rr + (col & 1)];
                    out[obase + col] = xv * (d * inv * gm[j] + bt[j]);
                }
            }
        }
        __syncthreads();
    }
}

extern "C" void kernel_launch(void* const* d_in, const int* in_sizes, int n_in,
                              void* d_out, int out_size) {
    const float* x     = (const float*)d_in[0];
    const float* W1    = (const float*)d_in[1];
    const float* W2    = (const float*)d_in[2];
    const float* gamma = (const float*)d_in[3];
    const float* beta  = (const float*)d_in[4];
    float* out = (float*)d_out;

    int rows   = in_sizes[0] / LDIM;     // 786432
    int ntiles = rows / TILE_R;          // 12288

    precompute_m1_kernel<<<LDIM, FDIM>>>(W1);

    const size_t smem_bytes =
        (size_t)(KP1 * FDIM + KP2 * LDIM + KP1 * ROWPAD + KP2 * ROWPAD) * sizeof(float2); // 223,488 B
    cudaFuncSetAttribute(fused_dct_mlp_ln_kernel,
                         cudaFuncAttributeMaxDynamicSharedMemorySize,
                         (int)smem_bytes);

    int nsm = 148;
    cudaDeviceGetAttribute(&nsm, cudaDevAttrMultiProcessorCount, 0);
    int grid = nsm;
    if (grid > ntiles) grid = ntiles;

    fused_dct_mlp_ln_kernel<<<grid, NTHREADS, smem_bytes>>>(x, W2, gamma, beta, out, ntiles);
}